// round 13
// baseline (speedup 1.0000x reference)
#include <cuda_runtime.h>
#include <cuda_bf16.h>
#include <cstdint>

#define NN 1024
#define SCALE_Y 1.6983709f   // sqrt(2*log2e); folded into W so G = 2log2e * XMX^T

__device__ __forceinline__ uint32_t smem_u32(const void* p) {
    uint32_t a;
    asm("{ .reg .u64 t; cvta.to.shared.u64 t, %1; cvt.u32.u64 %0, t; }" : "=r"(a) : "l"(p));
    return a;
}
__device__ __forceinline__ uint32_t swz128(uint32_t off) { return off ^ ((off >> 3) & 0x70); }

#define PACK_BF16X2(r, hi, lo) \
    asm("cvt.rn.bf16x2.f32 %0, %1, %2;" : "=r"(r) : "f"(hi), "f"(lo))

__device__ __forceinline__ void ldsm_x4(uint32_t r[4], uint32_t addr) {
    asm volatile("ldmatrix.sync.aligned.m8n8.x4.shared.b16 {%0,%1,%2,%3}, [%4];"
                 : "=r"(r[0]), "=r"(r[1]), "=r"(r[2]), "=r"(r[3]) : "r"(addr));
}
__device__ __forceinline__ void mma16816(float c[4], const uint32_t a[4],
                                         uint32_t b0, uint32_t b1) {
    asm volatile(
        "mma.sync.aligned.m16n8k16.row.col.f32.bf16.bf16.f32 "
        "{%0,%1,%2,%3}, {%4,%5,%6,%7}, {%8,%9}, {%0,%1,%2,%3};"
        : "+f"(c[0]), "+f"(c[1]), "+f"(c[2]), "+f"(c[3])
        : "r"(a[0]), "r"(a[1]), "r"(a[2]), "r"(a[3]), "r"(b0), "r"(b1));
}

// FFMA-only 2^t, deg-4 (abs err ~4e-5 on [-0.5,0.5]); FTZ clamp.
__device__ __forceinline__ float exp2_poly(float tt) {
    const float MAGIC = 12582912.0f;     // 2^23 + 2^22
    const int   MAGIC_I = 0x4B400000;
    float sh = tt + MAGIC;
    float rn = sh - MAGIC;
    float f  = tt - rn;
    int   n  = __float_as_int(sh) - MAGIC_I;
    float p = 9.6181291e-3f;
    p = fmaf(p, f, 5.5504109e-2f);
    p = fmaf(p, f, 2.4022651e-1f);
    p = fmaf(p, f, 6.9314718e-1f);
    p = fmaf(p, f, 1.0f);
    float sc = __int_as_float((n + 127) << 23);
    return (n < -126) ? 0.0f : p * sc;
}

// C(16-row strip x 64 cols) = A(strip, K-major) @ B(64 rows, K-major)^T, K=64.
__device__ __forceinline__ void gram16x64(float acc[8][4], uint32_t aBase,
                                          uint32_t bBase, int mrow0, int lane) {
    #pragma unroll
    for (int ks = 0; ks < 4; ks++) {
        uint32_t a[4];
        const int arow = mrow0 + ((lane >> 3) & 1) * 8 + (lane & 7);
        const int kba  = ks * 32 + (lane >> 4) * 16;
        ldsm_x4(a, aBase + swz128(arow * 128 + kba));
        #pragma unroll
        for (int nb2 = 0; nb2 < 4; nb2++) {
            uint32_t bf[4];
            const int nrow = nb2 * 16 + ((lane >> 4) & 1) * 8 + (lane & 7);
            const int kbb  = ks * 32 + ((lane >> 3) & 1) * 16;
            ldsm_x4(bf, bBase + swz128(nrow * 128 + kbb));
            mma16816(acc[nb2 * 2],     a, bf[0], bf[1]);
            mma16816(acc[nb2 * 2 + 1], a, bf[2], bf[3]);
        }
    }
}

// Store fp32 fragments as bf16 into a K-major swizzled tile (own strip only).
__device__ __forceinline__ void store_frag_bf16(char* tile, const float acc[8][4],
                                                int mrow0, int lane) {
    const int rloc = lane >> 2, cq = (lane & 3) * 2;
    #pragma unroll
    for (int nb = 0; nb < 8; nb++) {
        const int col = nb * 8 + cq;
        uint32_t u0, u1;
        PACK_BF16X2(u0, acc[nb][1], acc[nb][0]);
        PACK_BF16X2(u1, acc[nb][3], acc[nb][2]);
        *(uint32_t*)(tile + swz128((mrow0 + rloc) * 128 + col * 2))     = u0;
        *(uint32_t*)(tile + swz128((mrow0 + rloc + 8) * 128 + col * 2)) = u1;
    }
}

// R[row] = 0.5 * sum_a Tfrag[row,a] * X[row,a]  (X read back from bf16 tile).
__device__ __forceinline__ void rowdot_R(float* Rsh, const float acc[8][4],
                                         const char* xTile, int mrow0, int lane) {
    const int rloc = lane >> 2, cq = (lane & 3) * 2;
    const int r0 = mrow0 + rloc, r1 = r0 + 8;
    float s0 = 0.f, s1 = 0.f;
    #pragma unroll
    for (int nb = 0; nb < 8; nb++) {
        const int colb = (nb * 8 + cq) * 2;
        uint32_t u0 = *(const uint32_t*)(xTile + swz128(r0 * 128 + colb));
        uint32_t u1 = *(const uint32_t*)(xTile + swz128(r1 * 128 + colb));
        __nv_bfloat162 h0 = *reinterpret_cast<__nv_bfloat162*>(&u0);
        __nv_bfloat162 h1 = *reinterpret_cast<__nv_bfloat162*>(&u1);
        s0 = fmaf(acc[nb][0], __bfloat162float(h0.x),
             fmaf(acc[nb][1], __bfloat162float(h0.y), s0));
        s1 = fmaf(acc[nb][2], __bfloat162float(h1.x),
             fmaf(acc[nb][3], __bfloat162float(h1.y), s1));
    }
    s0 += __shfl_xor_sync(0xffffffffu, s0, 1);
    s0 += __shfl_xor_sync(0xffffffffu, s0, 2);
    s1 += __shfl_xor_sync(0xffffffffu, s1, 1);
    s1 += __shfl_xor_sync(0xffffffffu, s1, 2);
    if ((lane & 3) == 0) { Rsh[r0] = 0.5f * s0; Rsh[r1] = 0.5f * s1; }
}

// ---------------------------------------------------------------------------
// Fused kernel: per 64x64 triangular tile (ti >= tj), per batch:
//   Mh = Wh @ Wh^T;  T = X @ Mh (for i- and j-rows, R from frag dot);
//   G = Xi @ Tj^T;  adj = 2^(G - Ri - Rj), diag forced to 2; mirror if ti>tj.
// grid (136, 2), 128 threads.
// ---------------------------------------------------------------------------
__global__ void __launch_bounds__(128) adj_fused(const float* __restrict__ X,
                                                 const float* __restrict__ W,
                                                 float* __restrict__ out) {
    __shared__ __align__(1024) __nv_bfloat16 Xi[64 * 64];
    __shared__ __align__(1024) __nv_bfloat16 Xj[64 * 64];
    __shared__ __align__(1024) __nv_bfloat16 Wh[64 * 64];   // reused as Tj
    __shared__ __align__(1024) __nv_bfloat16 Mh[64 * 64];
    __shared__ float Rish[64], Rjsh[64];

    const int t = blockIdx.x, b = blockIdx.y;
    int ti = (int)((sqrtf(8.0f * (float)t + 1.0f) - 1.0f) * 0.5f);
    while ((ti + 1) * (ti + 2) / 2 <= t) ti++;
    while (ti * (ti + 1) / 2 > t) ti--;
    const int tj = t - ti * (ti + 1) / 2;

    const int tid = threadIdx.x;
    const int wid = tid >> 5, lane = tid & 31;
    const int gi = b * NN + ti * 64;
    const int gj = b * NN + tj * 64;

    // --- Loads: fp32 -> bf16, SW128-swizzled K-major tiles (all coalesced) ---
    const float4* xsI = (const float4*)(X + (size_t)gi * 64);
    const float4* xsJ = (const float4*)(X + (size_t)gj * 64);
    const float4* ws  = (const float4*)W;
    #pragma unroll
    for (int it = 0; it < 8; it++) {
        const int idx = tid + it * 128;       // 1024 float4 per tile
        const int row = idx >> 4, q = idx & 15;
        const uint32_t dstOff = swz128(row * 128 + q * 8);
        float4 f; uint32_t u0, u1;
        f = xsI[idx];
        PACK_BF16X2(u0, f.y, f.x); PACK_BF16X2(u1, f.w, f.z);
        *(uint2*)((char*)Xi + dstOff) = make_uint2(u0, u1);
        f = xsJ[idx];
        PACK_BF16X2(u0, f.y, f.x); PACK_BF16X2(u1, f.w, f.z);
        *(uint2*)((char*)Xj + dstOff) = make_uint2(u0, u1);
        f = ws[idx];
        f.x *= SCALE_Y; f.y *= SCALE_Y; f.z *= SCALE_Y; f.w *= SCALE_Y;
        PACK_BF16X2(u0, f.y, f.x); PACK_BF16X2(u1, f.w, f.z);
        *(uint2*)((char*)Wh + dstOff) = make_uint2(u0, u1);
    }
    __syncthreads();

    const uint32_t uXi = smem_u32(Xi), uXj = smem_u32(Xj);
    const uint32_t uWh = smem_u32(Wh), uMh = smem_u32(Mh);
    const int mrow0 = wid * 16;
    float acc[8][4];

    // --- Stage 1: Mh = Wh @ Wh^T (scaled metric) ---
    #pragma unroll
    for (int nb = 0; nb < 8; nb++)
        #pragma unroll
        for (int k = 0; k < 4; k++) acc[nb][k] = 0.f;
    gram16x64(acc, uWh, uWh, mrow0, lane);
    store_frag_bf16((char*)Mh, acc, mrow0, lane);
    __syncthreads();

    // --- Stage 2a: Ti = Xi @ Mh -> R_i only (fragments discarded) ---
    #pragma unroll
    for (int nb = 0; nb < 8; nb++)
        #pragma unroll
        for (int k = 0; k < 4; k++) acc[nb][k] = 0.f;
    gram16x64(acc, uXi, uMh, mrow0, lane);
    rowdot_R(Rish, acc, (const char*)Xi, mrow0, lane);

    // --- Stage 2b: Tj = Xj @ Mh -> R_j + store over Wh ---
    #pragma unroll
    for (int nb = 0; nb < 8; nb++)
        #pragma unroll
        for (int k = 0; k < 4; k++) acc[nb][k] = 0.f;
    gram16x64(acc, uXj, uMh, mrow0, lane);
    rowdot_R(Rjsh, acc, (const char*)Xj, mrow0, lane);
    store_frag_bf16((char*)Wh, acc, mrow0, lane);   // Wh now holds Tj
    __syncthreads();

    // --- Stage 3: G = Xi @ Tj^T ---
    #pragma unroll
    for (int nb = 0; nb < 8; nb++)
        #pragma unroll
        for (int k = 0; k < 4; k++) acc[nb][k] = 0.f;
    gram16x64(acc, uXi, uWh, mrow0, lane);

    // --- Epilogue ---
    const int rloc = lane >> 2;
    const float ri0 = Rish[mrow0 + rloc];
    const float ri1 = Rish[mrow0 + 8 + rloc];
    const bool diagTile = (ti == tj);
    const bool mirror = (ti > tj);
    const size_t outBase = (size_t)b * NN * NN;
    const int gRow0 = ti * 64 + mrow0 + rloc;
    const int colOff = tj * 64;
    const size_t o0 = outBase + (size_t)gRow0 * NN + colOff;
    const size_t o1 = o0 + 8u * NN;

    #pragma unroll
    for (int nb = 0; nb < 8; nb++) {
        const int col0 = nb * 8 + (lane & 3) * 2;
        const float rj0 = Rjsh[col0], rj1 = Rjsh[col0 + 1];
        float e00 = exp2_poly((acc[nb][0] - ri0) - rj0);
        float e01 = exp2_poly((acc[nb][1] - ri0) - rj1);
        float e10 = exp2_poly((acc[nb][2] - ri1) - rj0);
        float e11 = exp2_poly((acc[nb][3] - ri1) - rj1);
        const int gcol0 = colOff + col0;
        if (diagTile) {
            if (gRow0 == gcol0)         e00 = 2.0f;
            if (gRow0 == gcol0 + 1)     e01 = 2.0f;
            if (gRow0 + 8 == gcol0)     e10 = 2.0f;
            if (gRow0 + 8 == gcol0 + 1) e11 = 2.0f;
        }
        *(float2*)&out[o0 + col0] = make_float2(e00, e01);
        *(float2*)&out[o1 + col0] = make_float2(e10, e11);
        if (mirror) {
            out[outBase + (size_t)(gcol0)     * NN + gRow0]     = e00;
            out[outBase + (size_t)(gcol0 + 1) * NN + gRow0]     = e01;
            out[outBase + (size_t)(gcol0)     * NN + gRow0 + 8] = e10;
            out[outBase + (size_t)(gcol0 + 1) * NN + gRow0 + 8] = e11;
        }
    }
}

// ---------------------------------------------------------------------------
extern "C" void kernel_launch(void* const* d_in, const int* in_sizes, int n_in,
                              void* d_out, int out_size) {
    const float* X = (const float*)d_in[0];   // (2,1024,64)
    const float* W = (const float*)d_in[1];   // (64,64)
    float* out = (float*)d_out;               // (2,1024,1024)

    adj_fused<<<dim3(136, 2), 128>>>(X, W, out);
    (void)in_sizes; (void)n_in; (void)out_size;
}

// round 14
// speedup vs baseline: 1.4418x; 1.4418x over previous
#include <cuda_runtime.h>
#include <cuda_bf16.h>
#include <cstdint>

#define BATCH 2
#define NN 1024
#define ROWS (BATCH * NN)   // 2048
#define SCALE_Y 1.6983709f  // sqrt(2*log2e): t = <yh_i,yh_j> - R_i - R_j = -log2e*q

__device__ __nv_bfloat16 g_Yb[ROWS * 64];  // row-major, 128B rows
__device__ float g_R[ROWS];                // 0.5*||bf16(yh)||^2

__device__ __forceinline__ uint32_t smem_u32(const void* p) {
    uint32_t a;
    asm("{ .reg .u64 t; cvta.to.shared.u64 t, %1; cvt.u32.u64 %0, t; }" : "=r"(a) : "l"(p));
    return a;
}
__device__ __forceinline__ uint32_t swz128(uint32_t off) { return off ^ ((off >> 3) & 0x70); }

__device__ __forceinline__ void cpasync16(uint32_t dst, const void* src) {
    asm volatile("cp.async.cg.shared.global [%0], [%1], 16;" :: "r"(dst), "l"(src) : "memory");
}
__device__ __forceinline__ void cpasync4(uint32_t dst, const void* src) {
    asm volatile("cp.async.ca.shared.global [%0], [%1], 4;" :: "r"(dst), "l"(src) : "memory");
}

__device__ __forceinline__ void ldsm_x4(uint32_t r[4], uint32_t addr) {
    asm volatile("ldmatrix.sync.aligned.m8n8.x4.shared.b16 {%0,%1,%2,%3}, [%4];"
                 : "=r"(r[0]), "=r"(r[1]), "=r"(r[2]), "=r"(r[3]) : "r"(addr));
}
__device__ __forceinline__ void mma16816(float c[4], const uint32_t a[4],
                                         uint32_t b0, uint32_t b1) {
    asm volatile(
        "mma.sync.aligned.m16n8k16.row.col.f32.bf16.bf16.f32 "
        "{%0,%1,%2,%3}, {%4,%5,%6,%7}, {%8,%9}, {%0,%1,%2,%3};"
        : "+f"(c[0]), "+f"(c[1]), "+f"(c[2]), "+f"(c[3])
        : "r"(a[0]), "r"(a[1]), "r"(a[2]), "r"(a[3]), "r"(b0), "r"(b1));
}

// FFMA-only 2^t, deg-3 (ample precision: output is ~2*I + underflow tail).
__device__ __forceinline__ float exp2_poly(float tt) {
    const float MAGIC = 12582912.0f;     // 2^23 + 2^22
    const int   MAGIC_I = 0x4B400000;
    float sh = tt + MAGIC;
    float rn = sh - MAGIC;
    float f  = tt - rn;
    int   n  = __float_as_int(sh) - MAGIC_I;
    float p = 5.5504109e-2f;
    p = fmaf(p, f, 2.4022651e-1f);
    p = fmaf(p, f, 6.9314718e-1f);
    p = fmaf(p, f, 1.0f);
    float sc = __int_as_float((n + 127) << 23);
    return (n < -126) ? 0.0f : p * sc;
}

// ---------------------------------------------------------------------------
// Kernel A: yh = SCALE_Y * X @ W, bf16-rounded; R = 0.5*||bf16(yh)||^2.
// ---------------------------------------------------------------------------
__global__ void __launch_bounds__(128) y_kernel(const float* __restrict__ X,
                                                const float* __restrict__ W) {
    __shared__ float Ws[64 * 64];
    __shared__ float Xs[8 * 64];
    const int tid = threadIdx.x;
    const int rowBase = blockIdx.x * 8;

    #pragma unroll
    for (int i = tid; i < 1024; i += 128)
        ((float4*)Ws)[i] = ((const float4*)W)[i];
    if (tid < 128)
        ((float4*)Xs)[tid] = ((const float4*)(X + rowBase * 64))[tid];
    __syncthreads();

    const int warp = tid >> 5, lane = tid & 31;
    #pragma unroll
    for (int r = 0; r < 2; r++) {
        const int row = warp * 2 + r;
        float a0 = 0.f, a1 = 0.f;
        #pragma unroll
        for (int c0 = 0; c0 < 64; c0++) {
            const float xv = Xs[row * 64 + c0];
            a0 = fmaf(xv, Ws[c0 * 64 + lane],      a0);
            a1 = fmaf(xv, Ws[c0 * 64 + lane + 32], a1);
        }
        a0 *= SCALE_Y; a1 *= SCALE_Y;
        const __nv_bfloat16 b0 = __float2bfloat16(a0);
        const __nv_bfloat16 b1 = __float2bfloat16(a1);
        const float f0 = __bfloat162float(b0), f1 = __bfloat162float(b1);
        g_Yb[(rowBase + row) * 64 + lane]      = b0;
        g_Yb[(rowBase + row) * 64 + lane + 32] = b1;
        float s = f0 * f0 + f1 * f1;
        #pragma unroll
        for (int o = 16; o; o >>= 1) s += __shfl_xor_sync(0xffffffffu, s, o);
        if (lane == 0) g_R[rowBase + row] = 0.5f * s;
    }
}

// ---------------------------------------------------------------------------
// Tile compute: 64(i) x 32(j), 4 warps, mma.sync bf16, poly-exp, direct STG
// + register mirror for strictly sub-diagonal tiles.
// ---------------------------------------------------------------------------
__device__ __forceinline__ void compute_tile(
    const __nv_bfloat16* As, const __nv_bfloat16* Bs,
    const float* Rish, const float* Rjsh,
    int ti, int tj, int b, float* __restrict__ out, int tid)
{
    const int wid = tid >> 5, lane = tid & 31;
    const uint32_t aBase = smem_u32(As), bBase = smem_u32(Bs);
    const int mrow0 = wid * 16;

    float acc[4][4];
    #pragma unroll
    for (int nb = 0; nb < 4; nb++)
        #pragma unroll
        for (int k = 0; k < 4; k++) acc[nb][k] = 0.f;

    #pragma unroll
    for (int ks = 0; ks < 4; ks++) {
        uint32_t a[4];
        const int arow = mrow0 + ((lane >> 3) & 1) * 8 + (lane & 7);
        const int kba  = ks * 32 + (lane >> 4) * 16;
        ldsm_x4(a, aBase + swz128(arow * 128 + kba));
        #pragma unroll
        for (int nb2 = 0; nb2 < 2; nb2++) {
            uint32_t bf[4];
            const int nrow = nb2 * 16 + ((lane >> 4) & 1) * 8 + (lane & 7);
            const int kbb  = ks * 32 + ((lane >> 3) & 1) * 16;
            ldsm_x4(bf, bBase + swz128(nrow * 128 + kbb));
            mma16816(acc[nb2 * 2],     a, bf[0], bf[1]);
            mma16816(acc[nb2 * 2 + 1], a, bf[2], bf[3]);
        }
    }

    const int rloc = lane >> 2;
    const float ri0 = Rish[mrow0 + rloc];
    const float ri1 = Rish[mrow0 + 8 + rloc];
    const bool diagTile = (tj == 2 * ti || tj == 2 * ti + 1);
    const bool mirror = (tj < 2 * ti);
    const size_t outBase = (size_t)b * NN * NN;
    const int gRow0 = ti * 64 + mrow0 + rloc;
    const int colOff = tj * 32;
    const size_t o0 = outBase + (size_t)gRow0 * NN + colOff;
    const size_t o1 = o0 + 8u * NN;

    #pragma unroll
    for (int nb = 0; nb < 4; nb++) {
        const int col0 = nb * 8 + (lane & 3) * 2;
        const float rj0 = Rjsh[col0], rj1 = Rjsh[col0 + 1];
        float e00 = exp2_poly((acc[nb][0] - ri0) - rj0);
        float e01 = exp2_poly((acc[nb][1] - ri0) - rj1);
        float e10 = exp2_poly((acc[nb][2] - ri1) - rj0);
        float e11 = exp2_poly((acc[nb][3] - ri1) - rj1);
        const int gcol0 = colOff + col0;
        if (diagTile) {
            if (gRow0 == gcol0)         e00 = 2.0f;
            if (gRow0 == gcol0 + 1)     e01 = 2.0f;
            if (gRow0 + 8 == gcol0)     e10 = 2.0f;
            if (gRow0 + 8 == gcol0 + 1) e11 = 2.0f;
        }
        *(float2*)&out[o0 + col0] = make_float2(e00, e01);
        *(float2*)&out[o1 + col0] = make_float2(e10, e11);
        if (mirror) {
            out[outBase + (size_t)(gcol0)     * NN + gRow0]     = e00;
            out[outBase + (size_t)(gcol0 + 1) * NN + gRow0]     = e01;
            out[outBase + (size_t)(gcol0)     * NN + gRow0 + 8] = e10;
            out[outBase + (size_t)(gcol0 + 1) * NN + gRow0 + 8] = e11;
        }
    }
}

// ---------------------------------------------------------------------------
// Kernel B: 272 blocks x 128 thr. Block t handles triangular tile t for
// BOTH batches, double-buffered via cp.async: slot-1 loads are in flight
// during slot-0 compute (load latency hidden by pipelining, not occupancy).
// ---------------------------------------------------------------------------
__global__ void __launch_bounds__(128) adj_kernel(float* __restrict__ out) {
    __shared__ __align__(1024) __nv_bfloat16 As[2][64 * 64];
    __shared__ __align__(1024) __nv_bfloat16 Bs[2][32 * 64];
    __shared__ float Ri[2][64], Rj[2][32];

    const int t = blockIdx.x;
    int ti = (int)((sqrtf(4.0f * (float)t + 1.0f) - 1.0f) * 0.5f);
    while ((ti + 1) * (ti + 2) <= t) ti++;
    while (ti * (ti + 1) > t) ti--;
    const int tj = t - ti * (ti + 1);

    const int tid = threadIdx.x;

    // Prefetch both slots (slot s = batch s), each its own commit group.
    #pragma unroll
    for (int s = 0; s < 2; s++) {
        const int gi = s * NN + ti * 64;
        const int gj = s * NN + tj * 32;
        const uint32_t uA = smem_u32(As[s]), uB = smem_u32(Bs[s]);
        #pragma unroll
        for (int it = 0; it < 4; it++) {
            const int idx = tid + it * 128;          // A: 512 x 16B
            const int row = idx >> 3, ch = idx & 7;
            cpasync16(uA + swz128(row * 128 + ch * 16),
                      g_Yb + (size_t)(gi + row) * 64 + ch * 8);
        }
        #pragma unroll
        for (int it = 0; it < 2; it++) {
            const int idx = tid + it * 128;          // B: 256 x 16B
            const int row = idx >> 3, ch = idx & 7;
            cpasync16(uB + swz128(row * 128 + ch * 16),
                      g_Yb + (size_t)(gj + row) * 64 + ch * 8);
        }
        if (tid < 64)       cpasync4(smem_u32(&Ri[s][tid]),      g_R + gi + tid);
        else if (tid < 96)  cpasync4(smem_u32(&Rj[s][tid - 64]), g_R + gj + (tid - 64));
        asm volatile("cp.async.commit_group;" ::: "memory");
    }

    // Slot 0 ready (<=1 group pending), compute while slot 1 streams in.
    asm volatile("cp.async.wait_group 1;" ::: "memory");
    __syncthreads();
    compute_tile(As[0], Bs[0], Ri[0], Rj[0], ti, tj, 0, out, tid);

    asm volatile("cp.async.wait_group 0;" ::: "memory");
    __syncthreads();
    compute_tile(As[1], Bs[1], Ri[1], Rj[1], ti, tj, 1, out, tid);
}

// ---------------------------------------------------------------------------
extern "C" void kernel_launch(void* const* d_in, const int* in_sizes, int n_in,
                              void* d_out, int out_size) {
    const float* X = (const float*)d_in[0];   // (2,1024,64)
    const float* W = (const float*)d_in[1];   // (64,64)
    float* out = (float*)d_out;               // (2,1024,1024)

    y_kernel<<<256, 128>>>(X, W);
    adj_kernel<<<272, 128>>>(out);
    (void)in_sizes; (void)n_in; (void)out_size;
}